// round 3
// baseline (speedup 1.0000x reference)
#include <cuda_runtime.h>

#define NN 100000
#define NE 3200000
#define F  20
#define FP 24            // row padded to 96B = 3 aligned 32B sectors
#define SCAN_B 1024
#define NSCAN ((NN + SCAN_B - 1)/SCAN_B)   // 98

// ---------------- scratch (static __device__, no allocation) ----------------
__device__ int   g_rowptr[NN+1];
__device__ int   g_next[NN];
__device__ int   g_csrsrc[NE];
__device__ __align__(16) float g_h[NN*FP];
__device__ __align__(16) float g_g[NN*FP];
__device__ float g_as[NN];
__device__ float g_ad[NN];
__device__ int   g_bsum[128];

__device__ __forceinline__ float lrelu(float v) { return v > 0.f ? v : 0.2f*v; }

// ---------------- CSR build ----------------
__global__ void k_zero() {
    int i = blockIdx.x*blockDim.x + threadIdx.x;
    if (i < NN) g_next[i] = 0;
}

__global__ void k_hist(const int* __restrict__ dst) {
    int i = blockIdx.x*blockDim.x + threadIdx.x;
    if (i < NE) atomicAdd(&g_next[dst[i]], 1);
}

__global__ void k_scan1() {
    __shared__ int sh[SCAN_B];
    int t = threadIdx.x;
    int i = blockIdx.x*SCAN_B + t;
    int v = (i < NN) ? g_next[i] : 0;
    sh[t] = v; __syncthreads();
    #pragma unroll
    for (int off = 1; off < SCAN_B; off <<= 1) {
        int x = (t >= off) ? sh[t-off] : 0;
        __syncthreads();
        sh[t] += x;
        __syncthreads();
    }
    if (i < NN) g_rowptr[i] = sh[t] - v;           // exclusive, block-local
    if (t == SCAN_B-1) g_bsum[blockIdx.x] = sh[t]; // block total
}

__global__ void k_scan2() {
    __shared__ int sh[128];
    int t = threadIdx.x;
    int v = (t < NSCAN) ? g_bsum[t] : 0;
    sh[t] = v; __syncthreads();
    #pragma unroll
    for (int off = 1; off < 128; off <<= 1) {
        int x = (t >= off) ? sh[t-off] : 0;
        __syncthreads();
        sh[t] += x;
        __syncthreads();
    }
    if (t < NSCAN) g_bsum[t] = sh[t] - v;          // exclusive block offsets
}

__global__ void k_scan3() {
    int t = threadIdx.x;
    int i = blockIdx.x*SCAN_B + t;
    if (i < NN) {
        int r = g_rowptr[i] + g_bsum[blockIdx.x];
        g_rowptr[i] = r;
        g_next[i]   = r;   // scatter cursor
    }
    if (i == 0) g_rowptr[NN] = NE;
}

__global__ void k_scatter(const int* __restrict__ src,
                          const int* __restrict__ dst) {
    int i = blockIdx.x*blockDim.x + threadIdx.x;
    if (i < NE) {
        int d = dst[i];
        int p = atomicAdd(&g_next[d], 1);
        g_csrsrc[p] = src[i];
    }
}

// ---------------- layer 1 node transform (Fin = 1) ----------------
__global__ void k_node1(const float* __restrict__ x,
                        const float* __restrict__ W1,
                        const float* __restrict__ asv,
                        const float* __restrict__ adv) {
    int i = blockIdx.x*blockDim.x + threadIdx.x;
    if (i >= NN) return;
    float w[F];
    float cs = 0.f, cd = 0.f;
    #pragma unroll
    for (int j = 0; j < F; j++) { w[j] = W1[j]; cs += w[j]*asv[j]; cd += w[j]*adv[j]; }
    float xi = x[i];
    g_as[i] = xi*cs;
    g_ad[i] = xi*cd;
    float hv[FP];
    #pragma unroll
    for (int j = 0; j < F; j++) hv[j] = xi*w[j];
    #pragma unroll
    for (int j = F; j < FP; j++) hv[j] = 0.f;
    float4* o = (float4*)&g_h[i*FP];
    #pragma unroll
    for (int q = 0; q < FP/4; q++)
        o[q] = make_float4(hv[4*q], hv[4*q+1], hv[4*q+2], hv[4*q+3]);
}

// ---------------- online-softmax aggregation (thread per dst node) ----------
// Self-loop edge seeds the state: m = e_self, s = 1, acc = h[d].
__device__ __forceinline__ void agg_core(int d, float acc[F], float& s_out) {
    float add = g_ad[d];
    float m = lrelu(g_as[d] + add);
    float s = 1.f;
    {
        const float4* hd = (const float4*)&g_h[d*FP];
        #pragma unroll
        for (int q = 0; q < 5; q++) {
            float4 v = hd[q];
            acc[4*q] = v.x; acc[4*q+1] = v.y; acc[4*q+2] = v.z; acc[4*q+3] = v.w;
        }
    }
    int beg = g_rowptr[d], end = g_rowptr[d+1];
    for (int j = beg; j < end; j++) {
        int sn = g_csrsrc[j];
        float e  = lrelu(g_as[sn] + add);
        float mn = fmaxf(m, e);
        float sc = __expf(m - mn);
        float w  = __expf(e - mn);
        s = s*sc + w;
        const float4* hs = (const float4*)&g_h[sn*FP];
        #pragma unroll
        for (int q = 0; q < 5; q++) {
            float4 v = hs[q];
            acc[4*q]   = acc[4*q]  *sc + w*v.x;
            acc[4*q+1] = acc[4*q+1]*sc + w*v.y;
            acc[4*q+2] = acc[4*q+2]*sc + w*v.z;
            acc[4*q+3] = acc[4*q+3]*sc + w*v.w;
        }
        m = mn;
    }
    s_out = s;
}

__global__ void k_agg1(const float* __restrict__ b) {
    int d = blockIdx.x*blockDim.x + threadIdx.x;
    if (d >= NN) return;
    float acc[F]; float s;
    agg_core(d, acc, s);
    float inv = 1.f/(s + 1e-16f);
    float ov[FP];
    #pragma unroll
    for (int k = 0; k < F; k++) ov[k] = fmaxf(acc[k]*inv + b[k], 0.f);
    #pragma unroll
    for (int k = F; k < FP; k++) ov[k] = 0.f;
    float4* o = (float4*)&g_g[d*FP];
    #pragma unroll
    for (int q = 0; q < FP/4; q++)
        o[q] = make_float4(ov[4*q], ov[4*q+1], ov[4*q+2], ov[4*q+3]);
}

// ---------------- layer 2 node transform (20x20 GEMV per node) -------------
__global__ void k_node2(const float* __restrict__ W2,
                        const float* __restrict__ asv,
                        const float* __restrict__ adv) {
    __shared__ float sW[F*F];
    __shared__ float sA[F], sD[F];
    int t = threadIdx.x;
    for (int k = t; k < F*F; k += blockDim.x) sW[k] = W2[k];
    if (t < F) { sA[t] = asv[t]; sD[t] = adv[t]; }
    __syncthreads();

    int i = blockIdx.x*blockDim.x + t;
    if (i >= NN) return;
    float gin[F];
    const float4* gp = (const float4*)&g_g[i*FP];
    #pragma unroll
    for (int q = 0; q < 5; q++) {
        float4 v = gp[q];
        gin[4*q] = v.x; gin[4*q+1] = v.y; gin[4*q+2] = v.z; gin[4*q+3] = v.w;
    }
    float h2[F];
    #pragma unroll
    for (int j = 0; j < F; j++) {
        float acc = 0.f;
        #pragma unroll
        for (int k = 0; k < F; k++) acc += gin[k]*sW[k*F + j];
        h2[j] = acc;
    }
    float cs = 0.f, cd = 0.f;
    #pragma unroll
    for (int j = 0; j < F; j++) { cs += h2[j]*sA[j]; cd += h2[j]*sD[j]; }
    g_as[i] = cs;
    g_ad[i] = cd;
    float hv[FP];
    #pragma unroll
    for (int j = 0; j < F; j++) hv[j] = h2[j];
    #pragma unroll
    for (int j = F; j < FP; j++) hv[j] = 0.f;
    float4* o = (float4*)&g_h[i*FP];
    #pragma unroll
    for (int q = 0; q < FP/4; q++)
        o[q] = make_float4(hv[4*q], hv[4*q+1], hv[4*q+2], hv[4*q+3]);
}

// ---------------- layer 2 aggregation fused with final linear --------------
__global__ void k_agg2(const float* __restrict__ b,
                       const float* __restrict__ Wl,
                       const float* __restrict__ bl,
                       float* __restrict__ out) {
    int d = blockIdx.x*blockDim.x + threadIdx.x;
    if (d >= NN) return;
    float acc[F]; float s;
    agg_core(d, acc, s);
    float inv = 1.f/(s + 1e-16f);
    float o = bl[0];
    #pragma unroll
    for (int k = 0; k < F; k++)
        o += fmaxf(acc[k]*inv + b[k], 0.f) * Wl[k];
    out[d] = o;
}

// ---------------- launch ----------------
extern "C" void kernel_launch(void* const* d_in, const int* in_sizes, int n_in,
                              void* d_out, int out_size) {
    const float* x   = (const float*)d_in[0];
    const int*   ei  = (const int*)d_in[1];      // int32! (JAX x64 disabled)
    const float* W1  = (const float*)d_in[2];
    const float* as1 = (const float*)d_in[3];
    const float* ad1 = (const float*)d_in[4];
    const float* b1  = (const float*)d_in[5];
    const float* W2  = (const float*)d_in[6];
    const float* as2 = (const float*)d_in[7];
    const float* ad2 = (const float*)d_in[8];
    const float* b2  = (const float*)d_in[9];
    const float* Wl  = (const float*)d_in[10];
    const float* bl  = (const float*)d_in[11];
    float* out = (float*)d_out;

    const int* src = ei;
    const int* dst = ei + NE;

    int gN = (NN + 255)/256;
    int gE = (NE + 255)/256;

    // CSR build (shared by both layers)
    k_zero   <<<gN, 256>>>();
    k_hist   <<<gE, 256>>>(dst);
    k_scan1  <<<NSCAN, SCAN_B>>>();
    k_scan2  <<<1, 128>>>();
    k_scan3  <<<NSCAN, SCAN_B>>>();
    k_scatter<<<gE, 256>>>(src, dst);

    // layer 1
    k_node1<<<gN, 256>>>(x, W1, as1, ad1);
    k_agg1 <<<gN, 256>>>(b1);

    // layer 2 + fused output head
    k_node2<<<gN, 256>>>(W2, as2, ad2);
    k_agg2 <<<gN, 256>>>(b2, Wl, bl, out);
}

// round 4
// speedup vs baseline: 1.1012x; 1.1012x over previous
#include <cuda_runtime.h>

#define NN 100000
#define NE 3200000
#define F  20
#define FP 24            // row padded to 96B = 3 aligned 32B sectors
#define SCAN_B 1024
#define NSCAN ((NN + SCAN_B - 1)/SCAN_B)   // 98
#define G 8              // threads per destination node in aggregation

// ---------------- scratch (static __device__, no allocation) ----------------
__device__ int   g_rowptr[NN+1];
__device__ int   g_next[NN];
__device__ int   g_csrsrc[NE];
__device__ __align__(16) float g_h[NN*FP];
__device__ __align__(16) float g_g[NN*FP];
__device__ float g_as[NN];
__device__ float g_ad[NN];
__device__ int   g_bsum[128];

__device__ __forceinline__ float lrelu(float v) { return v > 0.f ? v : 0.2f*v; }

// ---------------- CSR build ----------------
__global__ void k_zero() {
    int i = blockIdx.x*blockDim.x + threadIdx.x;
    if (i < NN) g_next[i] = 0;
}

__global__ void k_hist(const int* __restrict__ dst) {
    int i = blockIdx.x*blockDim.x + threadIdx.x;
    if (i < NE) atomicAdd(&g_next[dst[i]], 1);
}

__global__ void k_scan1() {
    __shared__ int sh[SCAN_B];
    int t = threadIdx.x;
    int i = blockIdx.x*SCAN_B + t;
    int v = (i < NN) ? g_next[i] : 0;
    sh[t] = v; __syncthreads();
    #pragma unroll
    for (int off = 1; off < SCAN_B; off <<= 1) {
        int x = (t >= off) ? sh[t-off] : 0;
        __syncthreads();
        sh[t] += x;
        __syncthreads();
    }
    if (i < NN) g_rowptr[i] = sh[t] - v;           // exclusive, block-local
    if (t == SCAN_B-1) g_bsum[blockIdx.x] = sh[t]; // block total
}

__global__ void k_scan2() {
    __shared__ int sh[128];
    int t = threadIdx.x;
    int v = (t < NSCAN) ? g_bsum[t] : 0;
    sh[t] = v; __syncthreads();
    #pragma unroll
    for (int off = 1; off < 128; off <<= 1) {
        int x = (t >= off) ? sh[t-off] : 0;
        __syncthreads();
        sh[t] += x;
        __syncthreads();
    }
    if (t < NSCAN) g_bsum[t] = sh[t] - v;          // exclusive block offsets
}

__global__ void k_scan3() {
    int t = threadIdx.x;
    int i = blockIdx.x*SCAN_B + t;
    if (i < NN) {
        int r = g_rowptr[i] + g_bsum[blockIdx.x];
        g_rowptr[i] = r;
        g_next[i]   = r;   // scatter cursor
    }
    if (i == 0) g_rowptr[NN] = NE;
}

__global__ void k_scatter(const int* __restrict__ src,
                          const int* __restrict__ dst) {
    int i = blockIdx.x*blockDim.x + threadIdx.x;
    if (i < NE) {
        int d = dst[i];
        int p = atomicAdd(&g_next[d], 1);
        g_csrsrc[p] = src[i];
    }
}

// ---------------- layer 1 node transform (Fin = 1) ----------------
__global__ void k_node1(const float* __restrict__ x,
                        const float* __restrict__ W1,
                        const float* __restrict__ asv,
                        const float* __restrict__ adv) {
    int i = blockIdx.x*blockDim.x + threadIdx.x;
    if (i >= NN) return;
    float w[F];
    float cs = 0.f, cd = 0.f;
    #pragma unroll
    for (int j = 0; j < F; j++) { w[j] = W1[j]; cs += w[j]*asv[j]; cd += w[j]*adv[j]; }
    float xi = x[i];
    g_as[i] = xi*cs;
    g_ad[i] = xi*cd;
    float hv[FP];
    #pragma unroll
    for (int j = 0; j < F; j++) hv[j] = xi*w[j];
    #pragma unroll
    for (int j = F; j < FP; j++) hv[j] = 0.f;
    float4* o = (float4*)&g_h[i*FP];
    #pragma unroll
    for (int q = 0; q < FP/4; q++)
        o[q] = make_float4(hv[4*q], hv[4*q+1], hv[4*q+2], hv[4*q+3]);
}

// ---------------- sub-warp online-softmax aggregation ----------------------
// G threads per destination node. Each lane accumulates an online-softmax
// state over its strided slice of the CSR edges; states merge via shuffles.
__device__ __forceinline__ void state_merge(float& m, float& s, float acc[F], int off) {
    float mo = __shfl_down_sync(0xffffffffu, m, off, G);
    float so = __shfl_down_sync(0xffffffffu, s, off, G);
    float mn  = fmaxf(m, mo);
    float sc  = __expf(m  - mn);
    float sco = __expf(mo - mn);
    s = s*sc + so*sco;
    #pragma unroll
    for (int k = 0; k < F; k++) {
        float ao = __shfl_down_sync(0xffffffffu, acc[k], off, G);
        acc[k] = acc[k]*sc + ao*sco;
    }
    m = mn;
}

// Returns final (acc, s) valid on sub-lane 0 of each group.
__device__ __forceinline__ void agg_core_g(int d, int sub, float acc[F], float& s_out) {
    float add = g_ad[d];
    float m, s;
    if (sub == 0) {
        // self-loop edge seeds lane 0
        m = lrelu(g_as[d] + add);
        s = 1.f;
        const float4* hd = (const float4*)&g_h[d*FP];
        #pragma unroll
        for (int q = 0; q < 5; q++) {
            float4 v = hd[q];
            acc[4*q] = v.x; acc[4*q+1] = v.y; acc[4*q+2] = v.z; acc[4*q+3] = v.w;
        }
    } else {
        m = -1e30f; s = 0.f;
        #pragma unroll
        for (int k = 0; k < F; k++) acc[k] = 0.f;
    }
    int beg = g_rowptr[d], end = g_rowptr[d+1];
    for (int j = beg + sub; j < end; j += G) {
        int sn = g_csrsrc[j];
        float e  = lrelu(g_as[sn] + add);
        float mn = fmaxf(m, e);
        float sc = __expf(m - mn);
        float w  = __expf(e - mn);
        s = s*sc + w;
        const float4* hs = (const float4*)&g_h[sn*FP];
        #pragma unroll
        for (int q = 0; q < 5; q++) {
            float4 v = hs[q];
            acc[4*q]   = acc[4*q]  *sc + w*v.x;
            acc[4*q+1] = acc[4*q+1]*sc + w*v.y;
            acc[4*q+2] = acc[4*q+2]*sc + w*v.z;
            acc[4*q+3] = acc[4*q+3]*sc + w*v.w;
        }
        m = mn;
    }
    state_merge(m, s, acc, 4);
    state_merge(m, s, acc, 2);
    state_merge(m, s, acc, 1);
    s_out = s;
}

__global__ void k_agg1(const float* __restrict__ b) {
    int t = blockIdx.x*blockDim.x + threadIdx.x;
    int d = t / G, sub = t % G;
    if (d >= NN) return;
    float acc[F]; float s;
    agg_core_g(d, sub, acc, s);
    if (sub != 0) return;
    float inv = 1.f/(s + 1e-16f);
    float ov[FP];
    #pragma unroll
    for (int k = 0; k < F; k++) ov[k] = fmaxf(acc[k]*inv + b[k], 0.f);
    #pragma unroll
    for (int k = F; k < FP; k++) ov[k] = 0.f;
    float4* o = (float4*)&g_g[d*FP];
    #pragma unroll
    for (int q = 0; q < FP/4; q++)
        o[q] = make_float4(ov[4*q], ov[4*q+1], ov[4*q+2], ov[4*q+3]);
}

// ---------------- layer 2 node transform (20x20 GEMV per node) -------------
__global__ void k_node2(const float* __restrict__ W2,
                        const float* __restrict__ asv,
                        const float* __restrict__ adv) {
    __shared__ float sW[F*F];
    __shared__ float sA[F], sD[F];
    int t = threadIdx.x;
    for (int k = t; k < F*F; k += blockDim.x) sW[k] = W2[k];
    if (t < F) { sA[t] = asv[t]; sD[t] = adv[t]; }
    __syncthreads();

    int i = blockIdx.x*blockDim.x + t;
    if (i >= NN) return;
    float gin[F];
    const float4* gp = (const float4*)&g_g[i*FP];
    #pragma unroll
    for (int q = 0; q < 5; q++) {
        float4 v = gp[q];
        gin[4*q] = v.x; gin[4*q+1] = v.y; gin[4*q+2] = v.z; gin[4*q+3] = v.w;
    }
    float h2[F];
    #pragma unroll
    for (int j = 0; j < F; j++) {
        float acc = 0.f;
        #pragma unroll
        for (int k = 0; k < F; k++) acc += gin[k]*sW[k*F + j];
        h2[j] = acc;
    }
    float cs = 0.f, cd = 0.f;
    #pragma unroll
    for (int j = 0; j < F; j++) { cs += h2[j]*sA[j]; cd += h2[j]*sD[j]; }
    g_as[i] = cs;
    g_ad[i] = cd;
    float hv[FP];
    #pragma unroll
    for (int j = 0; j < F; j++) hv[j] = h2[j];
    #pragma unroll
    for (int j = F; j < FP; j++) hv[j] = 0.f;
    float4* o = (float4*)&g_h[i*FP];
    #pragma unroll
    for (int q = 0; q < FP/4; q++)
        o[q] = make_float4(hv[4*q], hv[4*q+1], hv[4*q+2], hv[4*q+3]);
}

// ---------------- layer 2 aggregation fused with final linear --------------
__global__ void k_agg2(const float* __restrict__ b,
                       const float* __restrict__ Wl,
                       const float* __restrict__ bl,
                       float* __restrict__ out) {
    int t = blockIdx.x*blockDim.x + threadIdx.x;
    int d = t / G, sub = t % G;
    if (d >= NN) return;
    float acc[F]; float s;
    agg_core_g(d, sub, acc, s);
    if (sub != 0) return;
    float inv = 1.f/(s + 1e-16f);
    float o = bl[0];
    #pragma unroll
    for (int k = 0; k < F; k++)
        o += fmaxf(acc[k]*inv + b[k], 0.f) * Wl[k];
    out[d] = o;
}

// ---------------- launch ----------------
extern "C" void kernel_launch(void* const* d_in, const int* in_sizes, int n_in,
                              void* d_out, int out_size) {
    const float* x   = (const float*)d_in[0];
    const int*   ei  = (const int*)d_in[1];      // int32 (JAX x64 disabled)
    const float* W1  = (const float*)d_in[2];
    const float* as1 = (const float*)d_in[3];
    const float* ad1 = (const float*)d_in[4];
    const float* b1  = (const float*)d_in[5];
    const float* W2  = (const float*)d_in[6];
    const float* as2 = (const float*)d_in[7];
    const float* ad2 = (const float*)d_in[8];
    const float* b2  = (const float*)d_in[9];
    const float* Wl  = (const float*)d_in[10];
    const float* bl  = (const float*)d_in[11];
    float* out = (float*)d_out;

    const int* src = ei;
    const int* dst = ei + NE;

    int gN = (NN + 255)/256;
    int gE = (NE + 255)/256;
    int gA = (NN*G + 255)/256;   // aggregation grid: G threads per node

    // CSR build (shared by both layers)
    k_zero   <<<gN, 256>>>();
    k_hist   <<<gE, 256>>>(dst);
    k_scan1  <<<NSCAN, SCAN_B>>>();
    k_scan2  <<<1, 128>>>();
    k_scan3  <<<NSCAN, SCAN_B>>>();
    k_scatter<<<gE, 256>>>(src, dst);

    // layer 1
    k_node1<<<gN, 256>>>(x, W1, as1, ad1);
    k_agg1 <<<gA, 256>>>(b1);

    // layer 2 + fused output head
    k_node2<<<gN, 256>>>(W2, as2, ad2);
    k_agg2 <<<gA, 256>>>(b2, Wl, bl, out);
}

// round 7
// speedup vs baseline: 1.4717x; 1.3364x over previous
#include <cuda_runtime.h>

#define NN 100000
#define NE 3200000
#define F  20
#define FP 24            // row = 96B = 3 aligned 32B sectors: [h(20), as, ad, pad, pad]
#define SCAN_B 1024
#define NSCAN ((NN + SCAN_B - 1)/SCAN_B)   // 98
#define G 8              // threads per destination node in aggregation

// ---------------- scratch (static __device__, no allocation) ----------------
__device__ int   g_rowptr[NN+1];
__device__ int   g_next[NN];
__device__ int   g_csrsrc[NE];
__device__ __align__(16) float g_h[NN*FP];
__device__ int   g_bsum[128];

__device__ __forceinline__ float lrelu(float v) { return v > 0.f ? v : 0.2f*v; }

// ---------------- CSR build ----------------
__global__ void k_zero() {
    int i = blockIdx.x*blockDim.x + threadIdx.x;
    if (i < NN) g_next[i] = 0;
}

__global__ void k_hist(const int* __restrict__ dst) {
    int i = blockIdx.x*blockDim.x + threadIdx.x;   // NE/4 threads
    int4 dv = ((const int4*)dst)[i];
    atomicAdd(&g_next[dv.x], 1);
    atomicAdd(&g_next[dv.y], 1);
    atomicAdd(&g_next[dv.z], 1);
    atomicAdd(&g_next[dv.w], 1);
}

// block-local exclusive scan via warp shuffles (2 barriers)
__global__ void k_scan1() {
    __shared__ int wsum[32];
    int t = threadIdx.x;
    int lane = t & 31, warp = t >> 5;
    int i = blockIdx.x*SCAN_B + t;
    int v = (i < NN) ? g_next[i] : 0;
    int xv = v;
    #pragma unroll
    for (int off = 1; off < 32; off <<= 1) {
        int y = __shfl_up_sync(0xffffffffu, xv, off);
        if (lane >= off) xv += y;
    }
    if (lane == 31) wsum[warp] = xv;
    __syncthreads();
    if (warp == 0) {
        int w = wsum[lane];
        #pragma unroll
        for (int off = 1; off < 32; off <<= 1) {
            int y = __shfl_up_sync(0xffffffffu, w, off);
            if (lane >= off) w += y;
        }
        wsum[lane] = w;
    }
    __syncthreads();
    int incl = xv + (warp > 0 ? wsum[warp-1] : 0);
    if (i < NN) g_rowptr[i] = incl - v;            // block-local exclusive
    if (t == SCAN_B-1) g_bsum[blockIdx.x] = incl;  // block total
}

// adds global block offsets (reduces g_bsum prefix in-kernel; replaces old scan2)
__global__ void k_scan3() {
    __shared__ int sh[128];
    int t = threadIdx.x, b = blockIdx.x;
    if (t < 128) sh[t] = (t < b) ? g_bsum[t] : 0;   // NSCAN=98 <= 128
    __syncthreads();
    #pragma unroll
    for (int o = 64; o > 0; o >>= 1) {
        if (t < o) sh[t] += sh[t+o];
        __syncthreads();
    }
    int off = sh[0];
    int i = b*SCAN_B + t;
    if (i < NN) {
        int r = g_rowptr[i] + off;
        g_rowptr[i] = r;
        g_next[i]   = r;   // scatter cursor
    }
    if (i == 0) g_rowptr[NN] = NE;
}

__global__ void k_scatter(const int* __restrict__ src,
                          const int* __restrict__ dst) {
    int i = blockIdx.x*blockDim.x + threadIdx.x;   // NE/4 threads
    int4 sv = ((const int4*)src)[i];
    int4 dv = ((const int4*)dst)[i];
    int p;
    p = atomicAdd(&g_next[dv.x], 1); g_csrsrc[p] = sv.x;
    p = atomicAdd(&g_next[dv.y], 1); g_csrsrc[p] = sv.y;
    p = atomicAdd(&g_next[dv.z], 1); g_csrsrc[p] = sv.z;
    p = atomicAdd(&g_next[dv.w], 1); g_csrsrc[p] = sv.w;
}

// ---------------- layer 1 aggregation + layer 2 node transform -------------
// Layer-1 h is rank-1 (Fin=1): h1[i] = x_i * w1, as1[i] = x_i*cs, ad1[i] = x_i*cd.
// So per edge we gather ONLY x[src] (4B) and accumulate scalars (m, s, S=sum w*x_src).
// Epilogue (all lanes, post-butterfly): feat = relu(w1*val + b1); h2 = feat@W2;
// row stored as [h2(20), as2, ad2, pad, pad].
__global__ void k_l1(const float* __restrict__ x,
                     const float* __restrict__ W1,
                     const float* __restrict__ as1,
                     const float* __restrict__ ad1,
                     const float* __restrict__ b1,
                     const float* __restrict__ W2,
                     const float* __restrict__ as2,
                     const float* __restrict__ ad2) {
    __shared__ float sW1[F], sB1[F], sW2[F*F], sA2[F], sD2[F];
    int t = threadIdx.x;
    for (int k = t; k < F; k += blockDim.x) {
        sW1[k] = W1[k]; sB1[k] = b1[k]; sA2[k] = as2[k]; sD2[k] = ad2[k];
    }
    for (int k = t; k < F*F; k += blockDim.x) sW2[k] = W2[k];
    __syncthreads();

    // cs1/cd1: uniform 20-term dots (broadcast loads, cheap)
    float cs = 0.f, cd = 0.f;
    #pragma unroll
    for (int k = 0; k < F; k++) { cs += sW1[k]*as1[k]; cd += sW1[k]*ad1[k]; }

    int gid = blockIdx.x*blockDim.x + t;   // grid sized exactly NN*G
    int d = gid / G, sub = gid & (G-1);

    float xd  = x[d];
    float add = xd * cd;
    float m, s, S;
    if (sub == 0) { m = lrelu(xd*cs + add); s = 1.f; S = xd; }  // self-loop seed
    else          { m = -1e30f; s = 0.f; S = 0.f; }

    int beg = g_rowptr[d], end = g_rowptr[d+1];
    for (int j = beg + sub; j < end; j += G) {
        float xs = x[g_csrsrc[j]];
        float e  = lrelu(xs*cs + add);
        float mn = fmaxf(m, e);
        float sc = __expf(m - mn);
        float w  = __expf(e - mn);
        s = s*sc + w;
        S = S*sc + w*xs;
        m = mn;
    }
    // butterfly merge -> all lanes hold final state
    #pragma unroll
    for (int off = G/2; off > 0; off >>= 1) {
        float mo = __shfl_xor_sync(0xffffffffu, m, off, G);
        float so = __shfl_xor_sync(0xffffffffu, s, off, G);
        float So = __shfl_xor_sync(0xffffffffu, S, off, G);
        float mn  = fmaxf(m, mo);
        float a   = __expf(m  - mn);
        float ao  = __expf(mo - mn);
        s = s*a + so*ao;
        S = S*a + So*ao;
        m = mn;
    }
    float val = S / (s + 1e-16f);

    float feat[F];
    #pragma unroll
    for (int k = 0; k < F; k++) feat[k] = fmaxf(sW1[k]*val + sB1[k], 0.f);

    // each lane computes columns j = sub, sub+8, sub+16(<20)
    float csp = 0.f, cdp = 0.f;
    float* row = &g_h[d*FP];
    #pragma unroll
    for (int r = 0; r < 3; r++) {
        int j = sub + 8*r;
        if (j < F) {
            float h2 = 0.f;
            #pragma unroll
            for (int k = 0; k < F; k++) h2 += feat[k]*sW2[k*F + j];
            row[j] = h2;
            csp += h2*sA2[j];
            cdp += h2*sD2[j];
        }
    }
    #pragma unroll
    for (int off = G/2; off > 0; off >>= 1) {
        csp += __shfl_xor_sync(0xffffffffu, csp, off, G);
        cdp += __shfl_xor_sync(0xffffffffu, cdp, off, G);
    }
    if (sub == 0) { row[F] = csp; row[F+1] = cdp; }
}

// ---------------- layer 2 aggregation + final linear -----------------------
// Per edge: ONE row gather (96B = 3 sectors) containing h2 + as; no separate as array.
__global__ void k_agg2(const float* __restrict__ b,
                       const float* __restrict__ Wl,
                       const float* __restrict__ bl,
                       float* __restrict__ out) {
    int gid = blockIdx.x*blockDim.x + threadIdx.x;
    int d = gid / G, sub = gid & (G-1);

    const float4* rd = (const float4*)&g_h[d*FP];
    float4 d0 = rd[0], d1 = rd[1], d2 = rd[2], d3 = rd[3], d4 = rd[4], d5 = rd[5];
    float add = d5.y;                         // ad of dst

    float m, s, acc[F];
    if (sub == 0) {
        m = lrelu(d5.x + add); s = 1.f;       // self-loop seed
        acc[0]=d0.x; acc[1]=d0.y; acc[2]=d0.z; acc[3]=d0.w;
        acc[4]=d1.x; acc[5]=d1.y; acc[6]=d1.z; acc[7]=d1.w;
        acc[8]=d2.x; acc[9]=d2.y; acc[10]=d2.z; acc[11]=d2.w;
        acc[12]=d3.x; acc[13]=d3.y; acc[14]=d3.z; acc[15]=d3.w;
        acc[16]=d4.x; acc[17]=d4.y; acc[18]=d4.z; acc[19]=d4.w;
    } else {
        m = -1e30f; s = 0.f;
        #pragma unroll
        for (int k = 0; k < F; k++) acc[k] = 0.f;
    }

    int beg = g_rowptr[d], end = g_rowptr[d+1];
    for (int j = beg + sub; j < end; j += G) {
        int sn = g_csrsrc[j];
        const float4* rs = (const float4*)&g_h[sn*FP];
        float4 s0 = rs[0], s1 = rs[1], s2 = rs[2], s3 = rs[3], s4 = rs[4], s5 = rs[5];
        float e  = lrelu(s5.x + add);
        float mn = fmaxf(m, e);
        float sc = __expf(m - mn);
        float w  = __expf(e - mn);
        s = s*sc + w;
        acc[0]=acc[0]*sc+w*s0.x;  acc[1]=acc[1]*sc+w*s0.y;  acc[2]=acc[2]*sc+w*s0.z;  acc[3]=acc[3]*sc+w*s0.w;
        acc[4]=acc[4]*sc+w*s1.x;  acc[5]=acc[5]*sc+w*s1.y;  acc[6]=acc[6]*sc+w*s1.z;  acc[7]=acc[7]*sc+w*s1.w;
        acc[8]=acc[8]*sc+w*s2.x;  acc[9]=acc[9]*sc+w*s2.y;  acc[10]=acc[10]*sc+w*s2.z; acc[11]=acc[11]*sc+w*s2.w;
        acc[12]=acc[12]*sc+w*s3.x; acc[13]=acc[13]*sc+w*s3.y; acc[14]=acc[14]*sc+w*s3.z; acc[15]=acc[15]*sc+w*s3.w;
        acc[16]=acc[16]*sc+w*s4.x; acc[17]=acc[17]*sc+w*s4.y; acc[18]=acc[18]*sc+w*s4.z; acc[19]=acc[19]*sc+w*s4.w;
        m = mn;
    }
    #pragma unroll
    for (int off = G/2; off > 0; off >>= 1) {
        float mo = __shfl_xor_sync(0xffffffffu, m, off, G);
        float so = __shfl_xor_sync(0xffffffffu, s, off, G);
        float mn  = fmaxf(m, mo);
        float a   = __expf(m  - mn);
        float ao  = __expf(mo - mn);
        s = s*a + so*ao;
        #pragma unroll
        for (int k = 0; k < F; k++) {
            float x = __shfl_xor_sync(0xffffffffu, acc[k], off, G);
            acc[k] = acc[k]*a + x*ao;
        }
        m = mn;
    }
    if (sub != 0) return;
    float inv = 1.f/(s + 1e-16f);
    float o = bl[0];
    #pragma unroll
    for (int k = 0; k < F; k++)
        o += fmaxf(acc[k]*inv + b[k], 0.f) * Wl[k];
    out[d] = o;
}

// ---------------- launch ----------------
extern "C" void kernel_launch(void* const* d_in, const int* in_sizes, int n_in,
                              void* d_out, int out_size) {
    const float* x   = (const float*)d_in[0];
    const int*   ei  = (const int*)d_in[1];      // int32 (JAX x64 disabled)
    const float* W1  = (const float*)d_in[2];
    const float* as1 = (const float*)d_in[3];
    const float* ad1 = (const float*)d_in[4];
    const float* b1  = (const float*)d_in[5];
    const float* W2  = (const float*)d_in[6];
    const float* as2 = (const float*)d_in[7];
    const float* ad2 = (const float*)d_in[8];
    const float* b2  = (const float*)d_in[9];
    const float* Wl  = (const float*)d_in[10];
    const float* bl  = (const float*)d_in[11];
    float* out = (float*)d_out;

    const int* src = ei;
    const int* dst = ei + NE;

    int gN  = (NN + 255)/256;
    int gE4 = (NE/4)/256;        // 3125 exactly
    int gA  = (NN*G)/256;        // 3125 exactly

    k_zero   <<<gN, 256>>>();
    k_hist   <<<gE4, 256>>>(dst);
    k_scan1  <<<NSCAN, SCAN_B>>>();
    k_scan3  <<<NSCAN, SCAN_B>>>();
    k_scatter<<<gE4, 256>>>(src, dst);

    k_l1  <<<gA, 256>>>(x, W1, as1, ad1, b1, W2, as2, ad2);
    k_agg2<<<gA, 256>>>(b2, Wl, bl, out);
}

// round 8
// speedup vs baseline: 1.4887x; 1.0116x over previous
#include <cuda_runtime.h>

#define NN 100000
#define NE 3200000
#define F  20
#define FP 24            // row = 96B = 3 aligned 32B sectors: [h(20), as, ad, pad, pad]
#define SCAN_B 1024
#define NSCAN ((NN + SCAN_B - 1)/SCAN_B)   // 98
#define G 8              // threads per destination node in aggregation

// ---------------- scratch (static __device__, no allocation) ----------------
__device__ int   g_rowptr[NN+1];
__device__ int   g_next[NN];
__device__ int   g_csrsrc[NE];
__device__ __align__(16) float g_h[NN*FP];
__device__ int   g_bsum[128];

__device__ __forceinline__ float lrelu(float v) { return v > 0.f ? v : 0.2f*v; }

// FMA-pipe-only exp (no MUFU). rel err ~2e-6 on the range used here.
__device__ __forceinline__ float fexp(float x) {
    x = fminf(fmaxf(x, -87.f), 87.f);
    float t = x * 1.4426950408889634f;          // x * log2(e)
    float r = t + 12582912.0f;                  // round-to-nearest (magic)
    int   n = __float_as_int(r) - 0x4B400000;   // integer part
    float f = t - (r - 12582912.0f);            // frac in [-0.5, 0.5]
    float p =            1.3333558e-3f;         // 2^f Taylor (ln2 powers)
    p = fmaf(p, f, 9.6181291e-3f);
    p = fmaf(p, f, 5.5504109e-2f);
    p = fmaf(p, f, 2.4022651e-1f);
    p = fmaf(p, f, 6.9314718e-1f);
    p = fmaf(p, f, 1.0f);
    return __int_as_float(__float_as_int(p) + (n << 23));
}

// ---------------- CSR build ----------------
__global__ void k_zero() {
    int i = blockIdx.x*blockDim.x + threadIdx.x;
    if (i < NN) g_next[i] = 0;
}

__global__ void k_hist(const int* __restrict__ dst) {
    int i = blockIdx.x*blockDim.x + threadIdx.x;   // NE/4 threads
    int4 dv = ((const int4*)dst)[i];
    atomicAdd(&g_next[dv.x], 1);
    atomicAdd(&g_next[dv.y], 1);
    atomicAdd(&g_next[dv.z], 1);
    atomicAdd(&g_next[dv.w], 1);
}

// block-local exclusive scan via warp shuffles
__global__ void k_scan1() {
    __shared__ int wsum[32];
    int t = threadIdx.x;
    int lane = t & 31, warp = t >> 5;
    int i = blockIdx.x*SCAN_B + t;
    int v = (i < NN) ? g_next[i] : 0;
    int xv = v;
    #pragma unroll
    for (int off = 1; off < 32; off <<= 1) {
        int y = __shfl_up_sync(0xffffffffu, xv, off);
        if (lane >= off) xv += y;
    }
    if (lane == 31) wsum[warp] = xv;
    __syncthreads();
    if (warp == 0) {
        int w = wsum[lane];
        #pragma unroll
        for (int off = 1; off < 32; off <<= 1) {
            int y = __shfl_up_sync(0xffffffffu, w, off);
            if (lane >= off) w += y;
        }
        wsum[lane] = w;
    }
    __syncthreads();
    int incl = xv + (warp > 0 ? wsum[warp-1] : 0);
    if (i < NN) g_rowptr[i] = incl - v;            // block-local exclusive
    if (t == SCAN_B-1) g_bsum[blockIdx.x] = incl;  // block total
}

// adds global block offsets (in-kernel reduction of predecessor block sums)
__global__ void k_scan3() {
    __shared__ int sh[128];
    int t = threadIdx.x, b = blockIdx.x;
    if (t < 128) sh[t] = (t < b) ? g_bsum[t] : 0;   // NSCAN=98 <= 128
    __syncthreads();
    #pragma unroll
    for (int o = 64; o > 0; o >>= 1) {
        if (t < o) sh[t] += sh[t+o];
        __syncthreads();
    }
    int off = sh[0];
    int i = b*SCAN_B + t;
    if (i < NN) {
        int r = g_rowptr[i] + off;
        g_rowptr[i] = r;
        g_next[i]   = r;   // scatter cursor
    }
    if (i == 0) g_rowptr[NN] = NE;
}

__global__ void k_scatter(const int* __restrict__ src,
                          const int* __restrict__ dst) {
    int i = blockIdx.x*blockDim.x + threadIdx.x;   // NE/4 threads
    int4 sv = ((const int4*)src)[i];
    int4 dv = ((const int4*)dst)[i];
    int p;
    p = atomicAdd(&g_next[dv.x], 1); g_csrsrc[p] = sv.x;
    p = atomicAdd(&g_next[dv.y], 1); g_csrsrc[p] = sv.y;
    p = atomicAdd(&g_next[dv.z], 1); g_csrsrc[p] = sv.z;
    p = atomicAdd(&g_next[dv.w], 1); g_csrsrc[p] = sv.w;
}

// ---------------- layer 1 aggregation + layer 2 node transform -------------
// Layer-1 h is rank-1 (Fin=1). Per edge: gather ONLY x[src] (4B); softmax
// shifted by the self-loop logit m0 (no online max) -> 1 fexp/edge, plain-add merges.
__global__ void k_l1(const float* __restrict__ x,
                     const float* __restrict__ W1,
                     const float* __restrict__ as1,
                     const float* __restrict__ ad1,
                     const float* __restrict__ b1,
                     const float* __restrict__ W2,
                     const float* __restrict__ as2,
                     const float* __restrict__ ad2) {
    __shared__ float sW1[F], sB1[F], sW2[F*F], sA2[F], sD2[F];
    int t = threadIdx.x;
    for (int k = t; k < F; k += blockDim.x) {
        sW1[k] = W1[k]; sB1[k] = b1[k]; sA2[k] = as2[k]; sD2[k] = ad2[k];
    }
    for (int k = t; k < F*F; k += blockDim.x) sW2[k] = W2[k];
    __syncthreads();

    float cs = 0.f, cd = 0.f;
    #pragma unroll
    for (int k = 0; k < F; k++) { cs += sW1[k]*as1[k]; cd += sW1[k]*ad1[k]; }

    int gid = blockIdx.x*blockDim.x + t;   // grid sized exactly NN*G
    int d = gid / G, sub = gid & (G-1);

    float xd  = x[d];
    float add = xd * cd;
    float m0  = lrelu(xd*cs + add);        // self-loop logit = shift
    float s = (sub == 0) ? 1.f : 0.f;      // exp(m0 - m0) = 1
    float S = (sub == 0) ? xd  : 0.f;

    int beg = g_rowptr[d], end = g_rowptr[d+1];
    for (int j = beg + sub; j < end; j += G) {
        float xs = x[g_csrsrc[j]];
        float w  = fexp(lrelu(xs*cs + add) - m0);
        s += w;
        S = fmaf(w, xs, S);
    }
    // butterfly sum -> all lanes hold totals
    #pragma unroll
    for (int off = G/2; off > 0; off >>= 1) {
        s += __shfl_xor_sync(0xffffffffu, s, off, G);
        S += __shfl_xor_sync(0xffffffffu, S, off, G);
    }
    float val = S / (s + 1e-16f);

    float feat[F];
    #pragma unroll
    for (int k = 0; k < F; k++) feat[k] = fmaxf(sW1[k]*val + sB1[k], 0.f);

    // each lane computes columns j = sub, sub+8, sub+16(<20)
    float csp = 0.f, cdp = 0.f;
    float* row = &g_h[d*FP];
    #pragma unroll
    for (int r = 0; r < 3; r++) {
        int j = sub + 8*r;
        if (j < F) {
            float h2 = 0.f;
            #pragma unroll
            for (int k = 0; k < F; k++) h2 += feat[k]*sW2[k*F + j];
            row[j] = h2;
            csp += h2*sA2[j];
            cdp += h2*sD2[j];
        }
    }
    #pragma unroll
    for (int off = G/2; off > 0; off >>= 1) {
        csp += __shfl_xor_sync(0xffffffffu, csp, off, G);
        cdp += __shfl_xor_sync(0xffffffffu, cdp, off, G);
    }
    if (sub == 0) { row[F] = csp; row[F+1] = cdp; }
}

// ---------------- layer 2 aggregation + final linear -----------------------
// Per edge: ONE 96B row gather (h2 + as fused). Self-logit shift, plain sums.
__global__ void k_agg2(const float* __restrict__ b,
                       const float* __restrict__ Wl,
                       const float* __restrict__ bl,
                       float* __restrict__ out) {
    int gid = blockIdx.x*blockDim.x + threadIdx.x;
    int d = gid / G, sub = gid & (G-1);

    const float4* rd = (const float4*)&g_h[d*FP];
    float4 d5 = rd[5];
    float add = d5.y;                      // ad of dst
    float m0  = lrelu(d5.x + add);         // self-loop logit = shift

    float s, acc[F];
    if (sub == 0) {
        s = 1.f;                           // self edge, w = 1
        float4 d0 = rd[0], d1 = rd[1], d2 = rd[2], d3 = rd[3], d4 = rd[4];
        acc[0]=d0.x; acc[1]=d0.y; acc[2]=d0.z; acc[3]=d0.w;
        acc[4]=d1.x; acc[5]=d1.y; acc[6]=d1.z; acc[7]=d1.w;
        acc[8]=d2.x; acc[9]=d2.y; acc[10]=d2.z; acc[11]=d2.w;
        acc[12]=d3.x; acc[13]=d3.y; acc[14]=d3.z; acc[15]=d3.w;
        acc[16]=d4.x; acc[17]=d4.y; acc[18]=d4.z; acc[19]=d4.w;
    } else {
        s = 0.f;
        #pragma unroll
        for (int k = 0; k < F; k++) acc[k] = 0.f;
    }

    int beg = g_rowptr[d], end = g_rowptr[d+1];
    for (int j = beg + sub; j < end; j += G) {
        int sn = g_csrsrc[j];
        const float4* rs = (const float4*)&g_h[sn*FP];
        float4 s5 = rs[5];
        float4 s0 = rs[0], s1 = rs[1], s2 = rs[2], s3 = rs[3], s4 = rs[4];
        float w = fexp(lrelu(s5.x + add) - m0);
        s += w;
        acc[0]=fmaf(w,s0.x,acc[0]);  acc[1]=fmaf(w,s0.y,acc[1]);  acc[2]=fmaf(w,s0.z,acc[2]);  acc[3]=fmaf(w,s0.w,acc[3]);
        acc[4]=fmaf(w,s1.x,acc[4]);  acc[5]=fmaf(w,s1.y,acc[5]);  acc[6]=fmaf(w,s1.z,acc[6]);  acc[7]=fmaf(w,s1.w,acc[7]);
        acc[8]=fmaf(w,s2.x,acc[8]);  acc[9]=fmaf(w,s2.y,acc[9]);  acc[10]=fmaf(w,s2.z,acc[10]); acc[11]=fmaf(w,s2.w,acc[11]);
        acc[12]=fmaf(w,s3.x,acc[12]); acc[13]=fmaf(w,s3.y,acc[13]); acc[14]=fmaf(w,s3.z,acc[14]); acc[15]=fmaf(w,s3.w,acc[15]);
        acc[16]=fmaf(w,s4.x,acc[16]); acc[17]=fmaf(w,s4.y,acc[17]); acc[18]=fmaf(w,s4.z,acc[18]); acc[19]=fmaf(w,s4.w,acc[19]);
    }
    // plain additive butterfly merge
    #pragma unroll
    for (int off = G/2; off > 0; off >>= 1) {
        s += __shfl_xor_sync(0xffffffffu, s, off, G);
        #pragma unroll
        for (int k = 0; k < F; k++)
            acc[k] += __shfl_xor_sync(0xffffffffu, acc[k], off, G);
    }
    if (sub != 0) return;
    float inv = 1.f/(s + 1e-16f);
    float o = bl[0];
    #pragma unroll
    for (int k = 0; k < F; k++)
        o += fmaxf(acc[k]*inv + b[k], 0.f) * Wl[k];
    out[d] = o;
}

// ---------------- launch ----------------
extern "C" void kernel_launch(void* const* d_in, const int* in_sizes, int n_in,
                              void* d_out, int out_size) {
    const float* x   = (const float*)d_in[0];
    const int*   ei  = (const int*)d_in[1];      // int32 (JAX x64 disabled)
    const float* W1  = (const float*)d_in[2];
    const float* as1 = (const float*)d_in[3];
    const float* ad1 = (const float*)d_in[4];
    const float* b1  = (const float*)d_in[5];
    const float* W2  = (const float*)d_in[6];
    const float* as2 = (const float*)d_in[7];
    const float* ad2 = (const float*)d_in[8];
    const float* b2  = (const float*)d_in[9];
    const float* Wl  = (const float*)d_in[10];
    const float* bl  = (const float*)d_in[11];
    float* out = (float*)d_out;

    const int* src = ei;
    const int* dst = ei + NE;

    int gN  = (NN + 255)/256;
    int gE4 = (NE/4)/256;        // 3125 exactly
    int gA  = (NN*G)/256;        // 3125 exactly

    k_zero   <<<gN, 256>>>();
    k_hist   <<<gE4, 256>>>(dst);
    k_scan1  <<<NSCAN, SCAN_B>>>();
    k_scan3  <<<NSCAN, SCAN_B>>>();
    k_scatter<<<gE4, 256>>>(src, dst);

    k_l1  <<<gA, 256>>>(x, W1, as1, ad1, b1, W2, as2, ad2);
    k_agg2<<<gA, 256>>>(b2, Wl, bl, out);
}

// round 10
// speedup vs baseline: 1.6279x; 1.0935x over previous
#include <cuda_runtime.h>

#define NN 100000
#define NE 3200000
#define F  20
#define FP 24            // row = 96B = 6 float4: [h(20), as, ad, pad, pad]
#define SCAN_B 1024
#define NSCAN ((NN + SCAN_B - 1)/SCAN_B)   // 98
#define G 8              // threads per destination node in aggregation

// ---------------- scratch (static __device__, no allocation) ----------------
__device__ int   g_rowptr[NN+1];
__device__ int   g_next[NN];
__device__ int   g_csrsrc[NE];
__device__ __align__(16) float g_h[NN*FP];
__device__ int   g_bsum[128];

__device__ __forceinline__ float lrelu(float v) { return v > 0.f ? v : 0.2f*v; }

// FMA-pipe exp (no MUFU). rel err ~2e-6 on the range used here.
__device__ __forceinline__ float fexp(float x) {
    x = fminf(fmaxf(x, -87.f), 87.f);
    float t = x * 1.4426950408889634f;
    float r = t + 12582912.0f;
    int   n = __float_as_int(r) - 0x4B400000;
    float f = t - (r - 12582912.0f);
    float p =            1.3333558e-3f;
    p = fmaf(p, f, 9.6181291e-3f);
    p = fmaf(p, f, 5.5504109e-2f);
    p = fmaf(p, f, 2.4022651e-1f);
    p = fmaf(p, f, 6.9314718e-1f);
    p = fmaf(p, f, 1.0f);
    return __int_as_float(__float_as_int(p) + (n << 23));
}

// ---------------- CSR build ----------------
__global__ void k_zero() {
    int i = blockIdx.x*blockDim.x + threadIdx.x;
    if (i < NN) g_next[i] = 0;
}

__global__ void k_hist(const int* __restrict__ dst) {
    int i = blockIdx.x*blockDim.x + threadIdx.x;   // NE/4 threads
    int4 dv = ((const int4*)dst)[i];
    atomicAdd(&g_next[dv.x], 1);
    atomicAdd(&g_next[dv.y], 1);
    atomicAdd(&g_next[dv.z], 1);
    atomicAdd(&g_next[dv.w], 1);
}

__global__ void k_scan1() {
    __shared__ int wsum[32];
    int t = threadIdx.x;
    int lane = t & 31, warp = t >> 5;
    int i = blockIdx.x*SCAN_B + t;
    int v = (i < NN) ? g_next[i] : 0;
    int xv = v;
    #pragma unroll
    for (int off = 1; off < 32; off <<= 1) {
        int y = __shfl_up_sync(0xffffffffu, xv, off);
        if (lane >= off) xv += y;
    }
    if (lane == 31) wsum[warp] = xv;
    __syncthreads();
    if (warp == 0) {
        int w = wsum[lane];
        #pragma unroll
        for (int off = 1; off < 32; off <<= 1) {
            int y = __shfl_up_sync(0xffffffffu, w, off);
            if (lane >= off) w += y;
        }
        wsum[lane] = w;
    }
    __syncthreads();
    int incl = xv + (warp > 0 ? wsum[warp-1] : 0);
    if (i < NN) g_rowptr[i] = incl - v;
    if (t == SCAN_B-1) g_bsum[blockIdx.x] = incl;
}

__global__ void k_scan3() {
    __shared__ int sh[128];
    int t = threadIdx.x, b = blockIdx.x;
    if (t < 128) sh[t] = (t < b) ? g_bsum[t] : 0;
    __syncthreads();
    #pragma unroll
    for (int o = 64; o > 0; o >>= 1) {
        if (t < o) sh[t] += sh[t+o];
        __syncthreads();
    }
    int off = sh[0];
    int i = b*SCAN_B + t;
    if (i < NN) {
        int r = g_rowptr[i] + off;
        g_rowptr[i] = r;
        g_next[i]   = r;
    }
    if (i == 0) g_rowptr[NN] = NE;
}

__global__ void k_scatter(const int* __restrict__ src,
                          const int* __restrict__ dst) {
    int i = blockIdx.x*blockDim.x + threadIdx.x;
    int4 sv = ((const int4*)src)[i];
    int4 dv = ((const int4*)dst)[i];
    int p;
    p = atomicAdd(&g_next[dv.x], 1); g_csrsrc[p] = sv.x;
    p = atomicAdd(&g_next[dv.y], 1); g_csrsrc[p] = sv.y;
    p = atomicAdd(&g_next[dv.z], 1); g_csrsrc[p] = sv.z;
    p = atomicAdd(&g_next[dv.w], 1); g_csrsrc[p] = sv.w;
}

// ---------------- layer 1 aggregation + layer 2 node transform -------------
// Per edge: gather ONLY x[src] (4B); softmax shifted by self-loop logit.
__global__ void k_l1(const float* __restrict__ x,
                     const float* __restrict__ W1,
                     const float* __restrict__ as1,
                     const float* __restrict__ ad1,
                     const float* __restrict__ b1,
                     const float* __restrict__ W2,
                     const float* __restrict__ as2,
                     const float* __restrict__ ad2) {
    __shared__ float sW1[F], sB1[F], sW2[F*F], sA2[F], sD2[F];
    int t = threadIdx.x;
    for (int k = t; k < F; k += blockDim.x) {
        sW1[k] = W1[k]; sB1[k] = b1[k]; sA2[k] = as2[k]; sD2[k] = ad2[k];
    }
    for (int k = t; k < F*F; k += blockDim.x) sW2[k] = W2[k];
    __syncthreads();

    float cs = 0.f, cd = 0.f;
    #pragma unroll
    for (int k = 0; k < F; k++) { cs += sW1[k]*as1[k]; cd += sW1[k]*ad1[k]; }

    int gid = blockIdx.x*blockDim.x + t;   // grid = NN*G exactly
    int d = gid / G, sub = gid & (G-1);
    unsigned gmask = 0xffu << ((t & 31) & ~7);   // this 8-lane group's mask

    float xd  = x[d];
    float add = xd * cd;
    float m0  = lrelu(xd*cs + add);
    float s = (sub == 0) ? 1.f : 0.f;
    float S = (sub == 0) ? xd  : 0.f;

    int beg = g_rowptr[d], end = g_rowptr[d+1];
    for (int j = beg + sub; j < end; j += G) {
        float xs = x[g_csrsrc[j]];
        float w  = fexp(lrelu(xs*cs + add) - m0);
        s += w;
        S = fmaf(w, xs, S);
    }
    #pragma unroll
    for (int off = G/2; off > 0; off >>= 1) {
        s += __shfl_xor_sync(gmask, s, off, G);
        S += __shfl_xor_sync(gmask, S, off, G);
    }
    float val = S / (s + 1e-16f);

    float feat[F];
    #pragma unroll
    for (int k = 0; k < F; k++) feat[k] = fmaxf(sW1[k]*val + sB1[k], 0.f);

    float csp = 0.f, cdp = 0.f;
    float* row = &g_h[d*FP];
    #pragma unroll
    for (int r = 0; r < 3; r++) {
        int j = sub + 8*r;
        if (j < F) {
            float h2 = 0.f;
            #pragma unroll
            for (int k = 0; k < F; k++) h2 += feat[k]*sW2[k*F + j];
            row[j] = h2;
            csp += h2*sA2[j];
            cdp += h2*sD2[j];
        }
    }
    #pragma unroll
    for (int off = G/2; off > 0; off >>= 1) {
        csp += __shfl_xor_sync(gmask, csp, off, G);
        cdp += __shfl_xor_sync(gmask, cdp, off, G);
    }
    if (sub == 0) { row[F] = csp; row[F+1] = cdp; }
}

// ---------------- layer 2 aggregation + final linear -----------------------
// COOPERATIVE: 8-lane group processes one edge at a time. Lanes 0-5 load one
// float4 each of the 96B row (coalesced); lane 5's .x/.y are as/ad. Each lane
// accumulates a 4-wide slice of the feature vector. All intra-loop shuffles
// use the group mask (groups in a warp have different trip counts!).
__global__ void k_agg2(const float* __restrict__ b,
                       const float* __restrict__ Wl,
                       const float* __restrict__ bl,
                       float* __restrict__ out) {
    int gid = blockIdx.x*blockDim.x + threadIdx.x;
    int d = gid / G, sub = gid & (G-1);
    unsigned gmask = 0xffu << ((threadIdx.x & 31) & ~7);
    bool ld = sub < 6;

    const float4* rows = (const float4*)g_h;

    // self row (seed, w = 1)
    float4 v0 = ld ? rows[d*6 + sub] : make_float4(0.f,0.f,0.f,0.f);
    float add = __shfl_sync(gmask, v0.y, 5, G);     // ad of dst
    float m0  = lrelu(__shfl_sync(gmask, v0.x, 5, G) + add);
    float s = 1.f;
    float a0 = v0.x, a1 = v0.y, a2 = v0.z, a3 = v0.w;

    int beg = g_rowptr[d], end = g_rowptr[d+1];
    int j = beg;
    for (; j + 1 < end; j += 2) {
        int sn0 = g_csrsrc[j];
        int sn1 = g_csrsrc[j+1];
        float4 va = ld ? rows[sn0*6 + sub] : make_float4(0.f,0.f,0.f,0.f);
        float4 vb = ld ? rows[sn1*6 + sub] : make_float4(0.f,0.f,0.f,0.f);
        float wa = fexp(lrelu(__shfl_sync(gmask, va.x, 5, G) + add) - m0);
        float wb = fexp(lrelu(__shfl_sync(gmask, vb.x, 5, G) + add) - m0);
        s += wa + wb;
        a0 = fmaf(wa, va.x, a0); a1 = fmaf(wa, va.y, a1);
        a2 = fmaf(wa, va.z, a2); a3 = fmaf(wa, va.w, a3);
        a0 = fmaf(wb, vb.x, a0); a1 = fmaf(wb, vb.y, a1);
        a2 = fmaf(wb, vb.z, a2); a3 = fmaf(wb, vb.w, a3);
    }
    if (j < end) {
        int sn0 = g_csrsrc[j];
        float4 va = ld ? rows[sn0*6 + sub] : make_float4(0.f,0.f,0.f,0.f);
        float wa = fexp(lrelu(__shfl_sync(gmask, va.x, 5, G) + add) - m0);
        s += wa;
        a0 = fmaf(wa, va.x, a0); a1 = fmaf(wa, va.y, a1);
        a2 = fmaf(wa, va.z, a2); a3 = fmaf(wa, va.w, a3);
    }

    // lanes 0..4 hold feature cols 4*sub .. 4*sub+3 (cols 0..19)
    float inv = 1.f/(s + 1e-16f);
    float o = 0.f;
    if (sub < 5) {
        int c = 4*sub;
        o  = fmaxf(a0*inv + b[c+0], 0.f) * Wl[c+0];
        o += fmaxf(a1*inv + b[c+1], 0.f) * Wl[c+1];
        o += fmaxf(a2*inv + b[c+2], 0.f) * Wl[c+2];
        o += fmaxf(a3*inv + b[c+3], 0.f) * Wl[c+3];
    }
    #pragma unroll
    for (int off = G/2; off > 0; off >>= 1)
        o += __shfl_xor_sync(gmask, o, off, G);
    if (sub == 0) out[d] = o + bl[0];
}

// ---------------- launch ----------------
extern "C" void kernel_launch(void* const* d_in, const int* in_sizes, int n_in,
                              void* d_out, int out_size) {
    const float* x   = (const float*)d_in[0];
    const int*   ei  = (const int*)d_in[1];
    const float* W1  = (const float*)d_in[2];
    const float* as1 = (const float*)d_in[3];
    const float* ad1 = (const float*)d_in[4];
    const float* b1  = (const float*)d_in[5];
    const float* W2  = (const float*)d_in[6];
    const float* as2 = (const float*)d_in[7];
    const float* ad2 = (const float*)d_in[8];
    const float* b2  = (const float*)d_in[9];
    const float* Wl  = (const float*)d_in[10];
    const float* bl  = (const float*)d_in[11];
    float* out = (float*)d_out;

    const int* src = ei;
    const int* dst = ei + NE;

    int gN  = (NN + 255)/256;
    int gE4 = (NE/4)/256;        // 3125 exactly
    int gA  = (NN*G)/256;        // 3125 exactly

    k_zero   <<<gN, 256>>>();
    k_hist   <<<gE4, 256>>>(dst);
    k_scan1  <<<NSCAN, SCAN_B>>>();
    k_scan3  <<<NSCAN, SCAN_B>>>();
    k_scatter<<<gE4, 256>>>(src, dst);

    k_l1  <<<gA, 256>>>(x, W1, as1, ad1, b1, W2, as2, ad2);
    k_agg2<<<gA, 256>>>(b2, Wl, bl, out);
}